// round 15
// baseline (speedup 1.0000x reference)
#include <cuda_runtime.h>
#include <cuda_fp16.h>
#include <cstdint>
#include <cstddef>
#include <cstring>

#define NN   50000
#define EE   600000
#define DD   128
#define OUTD 64
#define NB   ((NN + 255) / 256)   // 196 scan blocks

// PDL prologue: allow the next grid in the stream to begin launching, then
// wait for full memory visibility of the predecessor grid.
#define PDL_PROLOGUE() do {                                         \
    asm volatile("griddepcontrol.launch_dependents;");              \
    asm volatile("griddepcontrol.wait;" ::: "memory");              \
} while (0)

// ---------------------------------------------------------------------------
// Scratch state (no allocations allowed -> __device__ globals)
// ---------------------------------------------------------------------------
__device__ int      g_counts[NN];
__device__ int      g_rowoff[NN + 1];
__device__ unsigned g_packed[EE];          // (ordinal<<17) | dst ; ~0u invalid
__device__ int      g_csrsrc[EE];
__device__ float    g_deg[NN];
__device__ float    g_sdeg[NN];
__device__ uint2    g_f16a[(size_t)NN * DD / 4];   // z1 / z2
__device__ uint2    g_f16b[(size_t)NN * DD / 4];   // t  / u
__device__ uint2    g_f16c[(size_t)NN * DD / 4];   // h1 / h2
__device__ float    g_bW1[DD];
__device__ float    g_bW2[DD];
// Weight tiles in k-pair split-fp16 layout: element (p, n) packs
//   .x = half2( hi(W[2p][n]), hi(W[2p+1][n]) ), .y = half2( lo residuals )
__device__ float2   g_Wp1[(DD / 2) * DD];    // split(W1@W1)
__device__ float2   g_Wp2[(DD / 2) * DD];    // split(W2@W2)
__device__ float2   g_WpO[(DD / 2) * OUTD];  // split(Wout)
__device__ int      g_is32;                  // sticky: 1 iff int32 detected

// ---------------------------------------------------------------------------
// helpers
// ---------------------------------------------------------------------------
__device__ __forceinline__ unsigned h2_bits(__half2 h) {
    unsigned u; memcpy(&u, &h, 4); return u;
}

__device__ __forceinline__ float2 pack_pair(float w0, float w1) {
    __half h0 = __float2half_rn(w0), h1 = __float2half_rn(w1);
    float r0 = w0 - __half2float(h0);
    float r1 = w1 - __half2float(h1);
    __half2 hi = __halves2half2(h0, h1);
    __half2 lo = __floats2half2_rn(r0, r1);
    float2 o;
    o.x = __uint_as_float(h2_bits(hi));
    o.y = __uint_as_float(h2_bits(lo));
    return o;
}

__device__ __forceinline__ void mma_f16(float c[4], unsigned a0, unsigned a1,
                                        unsigned a2, unsigned a3,
                                        unsigned b0, unsigned b1) {
    asm volatile(
        "mma.sync.aligned.m16n8k16.row.col.f32.f16.f16.f32 "
        "{%0,%1,%2,%3}, {%4,%5,%6,%7}, {%8,%9}, {%0,%1,%2,%3};"
        : "+f"(c[0]), "+f"(c[1]), "+f"(c[2]), "+f"(c[3])
        : "r"(a0), "r"(a1), "r"(a2), "r"(a3), "r"(b0), "r"(b1));
}

__device__ __forceinline__ void split2(float2 a, unsigned& hi, unsigned& lo) {
    __half2 h = __floats2half2_rn(a.x, a.y);
    float r0 = a.x - __low2float(h);
    float r1 = a.y - __high2float(h);
    __half2 l = __floats2half2_rn(r0, r1);
    hi = h2_bits(h);
    lo = h2_bits(l);
}

__device__ __forceinline__ void add8(float* a, uint4 u) {
    __half2 h; float2 f;
    memcpy(&h, &u.x, 4); f = __half22float2(h); a[0] += f.x; a[1] += f.y;
    memcpy(&h, &u.y, 4); f = __half22float2(h); a[2] += f.x; a[3] += f.y;
    memcpy(&h, &u.z, 4); f = __half22float2(h); a[4] += f.x; a[5] += f.y;
    memcpy(&h, &u.w, 4); f = __half22float2(h); a[6] += f.x; a[7] += f.y;
}

__device__ __forceinline__ int load_edge(const void* ei, int idx, int is32) {
    if (is32) return ((const int*)ei)[idx];
    return (int)((const long long*)ei)[idx];
}

// 3x-split fp16 mainloop, fp32 A-smem tile (stride 132), split-W tile.
template <int NT, int WS>
__device__ __forceinline__ void tc_loop(const float* Asm, const float2* Wsm,
                                        int r0, int cb, int gid, int tig,
                                        float (*c)[4]) {
    #pragma unroll
    for (int ks = 0; ks < 8; ++ks) {
        int k0 = ks * 16;
        float2 aP0 = *(const float2*)(Asm + (r0 + gid) * 132 + k0 + 2 * tig);
        float2 aP1 = *(const float2*)(Asm + (r0 + gid + 8) * 132 + k0 + 2 * tig);
        float2 aP2 = *(const float2*)(Asm + (r0 + gid) * 132 + k0 + 2 * tig + 8);
        float2 aP3 = *(const float2*)(Asm + (r0 + gid + 8) * 132 + k0 + 2 * tig + 8);
        unsigned ah0, al0, ah1, al1, ah2, al2, ah3, al3;
        split2(aP0, ah0, al0);
        split2(aP1, ah1, al1);
        split2(aP2, ah2, al2);
        split2(aP3, ah3, al3);
        const float2* Wr0 = Wsm + (ks * 8 + tig) * WS + cb;
        const float2* Wr1 = Wsm + (ks * 8 + tig + 4) * WS + cb;
        #pragma unroll
        for (int nt = 0; nt < NT; ++nt) {
            float2 w0 = Wr0[nt * 8 + gid];
            float2 w1 = Wr1[nt * 8 + gid];
            unsigned bh0 = __float_as_uint(w0.x), bl0 = __float_as_uint(w0.y);
            unsigned bh1 = __float_as_uint(w1.x), bl1 = __float_as_uint(w1.y);
            mma_f16(c[nt], ah0, ah1, ah2, ah3, bh0, bh1);   // Ah*Wh
            mma_f16(c[nt], al0, al1, al2, al3, bh0, bh1);   // Al*Wh
            mma_f16(c[nt], ah0, ah1, ah2, ah3, bl0, bl1);   // Ah*Wl
        }
    }
}

// 2-term mainloop for EXACT fp16 A (lo(A) == 0): D = A*Wh + A*Wl.
template <int NT, int WS>
__device__ __forceinline__ void tc_loop16(const unsigned* Asm16,
                                          const float2* Wsm,
                                          int r0, int gid, int tig,
                                          float (*c)[4]) {
    #pragma unroll
    for (int ks = 0; ks < 8; ++ks) {
        int kp = ks * 8;
        unsigned a0 = Asm16[(r0 + gid) * 68 + kp + tig];
        unsigned a1 = Asm16[(r0 + gid + 8) * 68 + kp + tig];
        unsigned a2 = Asm16[(r0 + gid) * 68 + kp + tig + 4];
        unsigned a3 = Asm16[(r0 + gid + 8) * 68 + kp + tig + 4];
        const float2* Wr0 = Wsm + (kp + tig) * WS;
        const float2* Wr1 = Wsm + (kp + tig + 4) * WS;
        #pragma unroll
        for (int nt = 0; nt < NT; ++nt) {
            float2 w0 = Wr0[nt * 8 + gid];
            float2 w1 = Wr1[nt * 8 + gid];
            unsigned bh0 = __float_as_uint(w0.x), bl0 = __float_as_uint(w0.y);
            unsigned bh1 = __float_as_uint(w1.x), bl1 = __float_as_uint(w1.y);
            mma_f16(c[nt], a0, a1, a2, a3, bh0, bh1);   // A*Wh
            mma_f16(c[nt], a0, a1, a2, a3, bl0, bl1);   // A*Wl
        }
    }
}

// ---------------------------------------------------------------------------
// Init (no PDL wait; first kernel): [0,196): zero counts + int-width detect;
// [196,278): weight prep.
// ---------------------------------------------------------------------------
__global__ void k_init(const int* __restrict__ eiw,
                       const float* __restrict__ W1, const float* __restrict__ W2,
                       const float* __restrict__ Wout,
                       const float* __restrict__ b1, const float* __restrict__ b2) {
    asm volatile("griddepcontrol.launch_dependents;");
    int blk = blockIdx.x;
    int tid = threadIdx.x;
    if (blk < 196) {
        int i = blk * 256 + tid;
        if (i < NN) g_counts[i] = 0;
        if (i < 4096 && eiw[2 * i + 1] != 0) g_is32 = 1;   // sticky detect
    } else {
        int b = blk - 196;
        if (b < 64) {
            const float* W = (b < 32) ? W1 : W2;
            float2* O = (b < 32) ? g_Wp1 : g_Wp2;
            int idx = (b & 31) * 256 + tid;
            int pp = idx >> 7, n = idx & 127;
            int r0 = 2 * pp, r1 = 2 * pp + 1;
            float s0 = 0.f, s1 = 0.f;
            #pragma unroll 8
            for (int k = 0; k < DD; ++k) {
                float wc = W[k * DD + n];
                s0 += W[r0 * DD + k] * wc;
                s1 += W[r1 * DD + k] * wc;
            }
            O[idx] = pack_pair(s0, s1);
        } else if (b < 80) {
            int idx = (b - 64) * 256 + tid;
            int pp = idx >> 6, n = idx & 63;
            float w0 = Wout[(2 * pp) * OUTD + n];
            float w1 = Wout[(2 * pp + 1) * OUTD + n];
            g_WpO[idx] = pack_pair(w0, w1);
        } else {
            const float* bb = (b == 80) ? b1 : b2;
            const float* W  = (b == 80) ? W1 : W2;
            float* bw = (b == 80) ? g_bW1 : g_bW2;
            if (tid < DD) {
                float s = 0.f;
                #pragma unroll 8
                for (int k = 0; k < DD; ++k) s += bb[k] * W[k * DD + tid];
                bw[tid] = s;
            }
        }
    }
}

// Count in-degree; pack (ordinal<<17)|dst so k_fill never re-reads dst.
__global__ void k_count(const void* __restrict__ ei) {
    PDL_PROLOGUE();
    int e = blockIdx.x * blockDim.x + threadIdx.x;
    if (e >= EE) return;
    int is32 = g_is32;
    int dst = load_edge(ei, EE + e, is32);
    unsigned pk = 0xFFFFFFFFu;
    if ((unsigned)dst < (unsigned)NN) {
        int ord = atomicAdd(&g_counts[dst], 1);
        pk = ((unsigned)ord << 17) | (unsigned)dst;
    }
    g_packed[e] = pk;
}

// Self-summing scan: each block reduces counts[0 .. blockIdx*256) for its
// prefix (L2-resident), then local scan.
__global__ void k_rowoff() {
    PDL_PROLOGUE();
    __shared__ int ws[8];
    __shared__ int s_prefix;
    int tid = threadIdx.x;
    int lane = tid & 31, wid = tid >> 5;

    int lim = blockIdx.x * 256;
    int pi = 0;
    for (int j = tid; j < lim; j += 256) pi += g_counts[j];
    #pragma unroll
    for (int o = 16; o > 0; o >>= 1) pi += __shfl_down_sync(0xffffffffu, pi, o);
    if (lane == 0) ws[wid] = pi;
    __syncthreads();
    if (tid == 0) {
        int s = 0;
        #pragma unroll
        for (int w = 0; w < 8; ++w) s += ws[w];
        s_prefix = s;
    }
    __syncthreads();
    int prefix = s_prefix;
    __syncthreads();

    int i = blockIdx.x * 256 + tid;
    int v = (i < NN) ? g_counts[i] : 0;
    int x = v;
    #pragma unroll
    for (int o = 1; o < 32; o <<= 1) {
        int t = __shfl_up_sync(0xffffffffu, x, o);
        if (lane >= o) x += t;
    }
    if (lane == 31) ws[wid] = x;
    __syncthreads();
    if (wid == 0) {
        int y = (lane < 8) ? ws[lane] : 0;
        #pragma unroll
        for (int o = 1; o < 8; o <<= 1) {
            int t = __shfl_up_sync(0xffffffffu, y, o);
            if (lane >= o) y += t;
        }
        if (lane < 8) ws[lane] = y;
    }
    __syncthreads();
    int excl = x - v + (wid ? ws[wid - 1] : 0) + prefix;
    if (i < NN) {
        g_rowoff[i] = excl;
        g_deg[i] = (float)v;
        if (i == NN - 1) g_rowoff[NN] = excl + v;
    }
}

// Fill CSR — atomic-free; reads only src + packed(dst,ordinal).
__global__ void k_fill(const void* __restrict__ ei) {
    PDL_PROLOGUE();
    int e = blockIdx.x * blockDim.x + threadIdx.x;
    if (e >= EE) return;
    unsigned pk = g_packed[e];
    if (pk == 0xFFFFFFFFu) return;
    int dst = (int)(pk & 0x1FFFFu);
    int ord = (int)(pk >> 17);
    int is32 = g_is32;
    int src = load_edge(ei, e, is32);
    if ((unsigned)src >= (unsigned)NN) src = 0;
    g_csrsrc[g_rowoff[dst] + ord] = src;
}

// ---------------------------------------------------------------------------
// Aggregation over fp16 rows: 2 nodes per warp, 16 lanes x uint4 per node.
// ---------------------------------------------------------------------------
template <bool SDEG>
__device__ __forceinline__ void gather16(const uint4* __restrict__ in,
                                         int node, int l16, float* acc,
                                         float& sd) {
    int beg = g_rowoff[node], end = g_rowoff[node + 1];
    int e = beg;
    for (; e + 4 <= end; e += 4) {
        int s0 = g_csrsrc[e];
        int s1 = g_csrsrc[e + 1];
        int s2 = g_csrsrc[e + 2];
        int s3 = g_csrsrc[e + 3];
        uint4 u0 = in[(size_t)s0 * 16 + l16];
        uint4 u1 = in[(size_t)s1 * 16 + l16];
        uint4 u2 = in[(size_t)s2 * 16 + l16];
        uint4 u3 = in[(size_t)s3 * 16 + l16];
        if (SDEG) sd += (g_deg[s0] + g_deg[s1]) + (g_deg[s2] + g_deg[s3]);
        add8(acc, u0); add8(acc, u1); add8(acc, u2); add8(acc, u3);
    }
    for (; e < end; ++e) {
        int s0 = g_csrsrc[e];
        uint4 u0 = in[(size_t)s0 * 16 + l16];
        if (SDEG) sd += g_deg[s0];
        add8(acc, u0);
    }
}

__device__ __forceinline__ uint4 pack8(const float* a) {
    uint4 o;
    o.x = h2_bits(__floats2half2_rn(a[0], a[1]));
    o.y = h2_bits(__floats2half2_rn(a[2], a[3]));
    o.z = h2_bits(__floats2half2_rn(a[4], a[5]));
    o.w = h2_bits(__floats2half2_rn(a[6], a[7]));
    return o;
}

// Plain gather -> fp16 (optionally computing sdeg on pass 1)
template <bool SDEG>
__global__ void __launch_bounds__(256) k_agg_hh(const uint4* __restrict__ in,
                                                uint4* __restrict__ out) {
    PDL_PROLOGUE();
    int gw = (blockIdx.x * blockDim.x + threadIdx.x) >> 5;
    int lane = threadIdx.x & 31;
    int node = gw * 2 + (lane >> 4);
    int l16 = lane & 15;
    if (node >= NN) return;
    float acc[8] = {0.f, 0.f, 0.f, 0.f, 0.f, 0.f, 0.f, 0.f};
    float sd = 0.f;
    gather16<SDEG>(in, node, l16, acc, sd);
    out[(size_t)node * 16 + l16] = pack8(acc);
    if (SDEG && l16 == 0) g_sdeg[node] = sd;
}

// Gather + pool epilogue: h = relu(acc + sdeg*bw + deg*bv) -> fp16
__global__ void __launch_bounds__(256) k_agg_epi(const uint4* __restrict__ in,
                                                 const float* __restrict__ bw,
                                                 const float* __restrict__ bv,
                                                 uint4* __restrict__ out) {
    PDL_PROLOGUE();
    int gw = (blockIdx.x * blockDim.x + threadIdx.x) >> 5;
    int lane = threadIdx.x & 31;
    int node = gw * 2 + (lane >> 4);
    int l16 = lane & 15;
    if (node >= NN) return;
    float acc[8] = {0.f, 0.f, 0.f, 0.f, 0.f, 0.f, 0.f, 0.f};
    float sd = 0.f;
    gather16<false>(in, node, l16, acc, sd);
    float s = g_sdeg[node], d = g_deg[node];
    float4 bwa = ((const float4*)bw)[l16 * 2];
    float4 bwb = ((const float4*)bw)[l16 * 2 + 1];
    float4 bva = ((const float4*)bv)[l16 * 2];
    float4 bvb = ((const float4*)bv)[l16 * 2 + 1];
    acc[0] = fmaxf(acc[0] + s * bwa.x + d * bva.x, 0.f);
    acc[1] = fmaxf(acc[1] + s * bwa.y + d * bva.y, 0.f);
    acc[2] = fmaxf(acc[2] + s * bwa.z + d * bva.z, 0.f);
    acc[3] = fmaxf(acc[3] + s * bwa.w + d * bva.w, 0.f);
    acc[4] = fmaxf(acc[4] + s * bwb.x + d * bvb.x, 0.f);
    acc[5] = fmaxf(acc[5] + s * bwb.y + d * bvb.y, 0.f);
    acc[6] = fmaxf(acc[6] + s * bwb.z + d * bvb.z, 0.f);
    acc[7] = fmaxf(acc[7] + s * bwb.w + d * bvb.w, 0.f);
    out[(size_t)node * 16 + l16] = pack8(acc);
}

// ---------------------------------------------------------------------------
// GEMM 1: z1 = x @ Wp1  (fp32 A, 3-term, no bias), fp16 out. 64x128 tile.
// ---------------------------------------------------------------------------
__global__ void __launch_bounds__(256, 2)
k_gemm_x(const float* __restrict__ A, const float2* __restrict__ Wp,
         unsigned* __restrict__ C16) {
    PDL_PROLOGUE();
    extern __shared__ char smraw[];
    float*  Asm = (float*)smraw;                               // [64][132]
    float2* Wsm = (float2*)(smraw + 64 * 132 * sizeof(float)); // [64][132]

    const int tid = threadIdx.x;
    const int row0 = blockIdx.x * 64;

    #pragma unroll 4
    for (int idx = tid; idx < 64 * 128; idx += 256) {
        int p = idx >> 7, n = idx & 127;
        Wsm[p * 132 + n] = Wp[idx];
    }
    {
        const float4* Ag = (const float4*)A;
        #pragma unroll
        for (int it = 0; it < 8; ++it) {
            int idx = it * 256 + tid;
            int r = idx >> 5, kq = idx & 31;
            float4 v = make_float4(0.f, 0.f, 0.f, 0.f);
            if (row0 + r < NN) v = Ag[(size_t)(row0 + r) * 32 + kq];
            *(float4*)(Asm + r * 132 + kq * 4) = v;
        }
    }
    __syncthreads();

    const int warp = tid >> 5, lane = tid & 31;
    const int gid = lane >> 2, tig = lane & 3;
    const int r0 = (warp & 3) * 16;
    const int cb = (warp >> 2) * 64;

    float c[8][4];
    #pragma unroll
    for (int nt = 0; nt < 8; ++nt)
        #pragma unroll
        for (int q = 0; q < 4; ++q) c[nt][q] = 0.f;

    tc_loop<8, 132>(Asm, Wsm, r0, cb, gid, tig, c);

    int rA = row0 + r0 + gid;
    int rB = rA + 8;
    #pragma unroll
    for (int nt = 0; nt < 8; ++nt) {
        int col = cb + nt * 8 + 2 * tig;
        if (rA < NN)
            C16[(size_t)rA * 64 + (col >> 1)] =
                h2_bits(__floats2half2_rn(c[nt][0], c[nt][1]));
        if (rB < NN)
            C16[(size_t)rB * 64 + (col >> 1)] =
                h2_bits(__floats2half2_rn(c[nt][2], c[nt][3]));
    }
}

// ---------------------------------------------------------------------------
// GEMM 2: z2 = h1 @ Wp2  (EXACT fp16 A, 2-term), fp16 out. 128x128 tile.
// ---------------------------------------------------------------------------
__global__ void __launch_bounds__(256, 2)
k_gemm_h(const uint2* __restrict__ A16, const float2* __restrict__ Wp,
         unsigned* __restrict__ C16) {
    PDL_PROLOGUE();
    extern __shared__ char smraw[];
    unsigned* Asm16 = (unsigned*)smraw;                             // [128][68]
    float2*   Wsm = (float2*)(smraw + 128 * 68 * sizeof(unsigned)); // [64][132]

    const int tid = threadIdx.x;
    const int row0 = blockIdx.x * 128;

    #pragma unroll 8
    for (int idx = tid; idx < 64 * 128; idx += 256) {
        int p = idx >> 7, n = idx & 127;
        Wsm[p * 132 + n] = Wp[idx];
    }
    {
        const uint4* Ag = (const uint4*)A16;
        #pragma unroll
        for (int it = 0; it < 8; ++it) {
            int idx = it * 256 + tid;
            int r = idx >> 4, q = idx & 15;
            uint4 v = make_uint4(0u, 0u, 0u, 0u);
            if (row0 + r < NN) v = Ag[(size_t)(row0 + r) * 16 + q];
            *(uint4*)(Asm16 + r * 68 + q * 4) = v;
        }
    }
    __syncthreads();

    const int warp = tid >> 5, lane = tid & 31;
    const int gid = lane >> 2, tig = lane & 3;
    const int r0 = warp * 16;

    float c[16][4];
    #pragma unroll
    for (int nt = 0; nt < 16; ++nt)
        #pragma unroll
        for (int q = 0; q < 4; ++q) c[nt][q] = 0.f;

    tc_loop16<16, 132>(Asm16, Wsm, r0, gid, tig, c);

    int rA = row0 + r0 + gid;
    int rB = rA + 8;
    #pragma unroll
    for (int nt = 0; nt < 16; ++nt) {
        int col = nt * 8 + 2 * tig;
        if (rA < NN)
            C16[(size_t)rA * 64 + (col >> 1)] =
                h2_bits(__floats2half2_rn(c[nt][0], c[nt][1]));
        if (rB < NN)
            C16[(size_t)rB * 64 + (col >> 1)] =
                h2_bits(__floats2half2_rn(c[nt][2], c[nt][3]));
    }
}

// ---------------------------------------------------------------------------
// GEMM out: out = h2 @ WpO + bout  (EXACT fp16 A, 2-term), fp32 out.
// ---------------------------------------------------------------------------
__global__ void __launch_bounds__(256, 2)
k_gemm_out(const uint2* __restrict__ A16, const float2* __restrict__ WpO,
           const float* __restrict__ bvo, float* __restrict__ out) {
    PDL_PROLOGUE();
    extern __shared__ char smraw[];
    unsigned* Asm16 = (unsigned*)smraw;                             // [128][68]
    float2*   Wsm = (float2*)(smraw + 128 * 68 * sizeof(unsigned)); // [64][68]

    const int tid = threadIdx.x;
    const int row0 = blockIdx.x * 128;

    #pragma unroll 4
    for (int idx = tid; idx < 64 * 64; idx += 256) {
        int p = idx >> 6, n = idx & 63;
        Wsm[p * 68 + n] = WpO[idx];
    }
    {
        const uint4* Ag = (const uint4*)A16;
        #pragma unroll
        for (int it = 0; it < 8; ++it) {
            int idx = it * 256 + tid;
            int r = idx >> 4, q = idx & 15;
            uint4 v = make_uint4(0u, 0u, 0u, 0u);
            if (row0 + r < NN) v = Ag[(size_t)(row0 + r) * 16 + q];
            *(uint4*)(Asm16 + r * 68 + q * 4) = v;
        }
    }
    __syncthreads();

    const int warp = tid >> 5, lane = tid & 31;
    const int gid = lane >> 2, tig = lane & 3;
    const int r0 = warp * 16;

    float c[8][4];
    #pragma unroll
    for (int nt = 0; nt < 8; ++nt)
        #pragma unroll
        for (int q = 0; q < 4; ++q) c[nt][q] = 0.f;

    tc_loop16<8, 68>(Asm16, Wsm, r0, gid, tig, c);

    int rA = row0 + r0 + gid;
    int rB = rA + 8;
    #pragma unroll
    for (int nt = 0; nt < 8; ++nt) {
        int col = nt * 8 + 2 * tig;
        float v0 = bvo[col], v1 = bvo[col + 1];
        if (rA < NN)
            *(float2*)&out[(size_t)rA * OUTD + col] =
                make_float2(c[nt][0] + v0, c[nt][1] + v1);
        if (rB < NN)
            *(float2*)&out[(size_t)rB * OUTD + col] =
                make_float2(c[nt][2] + v0, c[nt][3] + v1);
    }
}

// ---------------------------------------------------------------------------
// Launch: 11 kernels, PDL-chained
// ---------------------------------------------------------------------------
template <typename K, typename... Args>
static void launch_pdl(K kernel, int grid, int block, size_t smem, bool pdl,
                       Args... args) {
    cudaLaunchConfig_t cfg = {};
    cfg.gridDim = dim3(grid, 1, 1);
    cfg.blockDim = dim3(block, 1, 1);
    cfg.dynamicSmemBytes = smem;
    cfg.stream = 0;
    cudaLaunchAttribute at[1];
    at[0].id = cudaLaunchAttributeProgrammaticStreamSerialization;
    at[0].val.programmaticStreamSerializationAllowed = 1;
    cfg.attrs = pdl ? at : nullptr;
    cfg.numAttrs = pdl ? 1 : 0;
    cudaLaunchKernelEx(&cfg, kernel, args...);
}

extern "C" void kernel_launch(void* const* d_in, const int* in_sizes, int n_in,
                              void* d_out, int out_size) {
    const float* x    = (const float*)d_in[0];
    const void*  ei   = d_in[1];
    const float* W1   = (const float*)d_in[2];
    const float* b1   = (const float*)d_in[3];
    const float* W2   = (const float*)d_in[4];
    const float* b2   = (const float*)d_in[5];
    const float* Wout = (const float*)d_in[6];
    const float* bout = (const float*)d_in[7];
    float* out = (float*)d_out;

    void *pbW1, *pbW2, *pWp1, *pWp2, *pWpO, *pa, *pb, *pc;
    cudaGetSymbolAddress(&pbW1, g_bW1);
    cudaGetSymbolAddress(&pbW2, g_bW2);
    cudaGetSymbolAddress(&pWp1, g_Wp1);
    cudaGetSymbolAddress(&pWp2, g_Wp2);
    cudaGetSymbolAddress(&pWpO, g_WpO);
    cudaGetSymbolAddress(&pa, g_f16a);
    cudaGetSymbolAddress(&pb, g_f16b);
    cudaGetSymbolAddress(&pc, g_f16c);
    float*  bW1 = (float*)pbW1;
    float*  bW2 = (float*)pbW2;
    float2* Wp1 = (float2*)pWp1;
    float2* Wp2 = (float2*)pWp2;
    float2* WpO = (float2*)pWpO;
    uint2*  f16a = (uint2*)pa;
    uint2*  f16b = (uint2*)pb;
    uint2*  f16c = (uint2*)pc;

    const size_t SMX = 64 * 132 * sizeof(float) + 64 * 132 * sizeof(float2);    // ~99 KB
    const size_t SMH = 128 * 68 * sizeof(unsigned) + 64 * 132 * sizeof(float2); // 100 KB
    const size_t SMO = 128 * 68 * sizeof(unsigned) + 64 * 68 * sizeof(float2);  // ~68 KB
    cudaFuncSetAttribute(k_gemm_x,
                         cudaFuncAttributeMaxDynamicSharedMemorySize, (int)SMX);
    cudaFuncSetAttribute(k_gemm_h,
                         cudaFuncAttributeMaxDynamicSharedMemorySize, (int)SMH);
    cudaFuncSetAttribute(k_gemm_out,
                         cudaFuncAttributeMaxDynamicSharedMemorySize, (int)SMO);

    const int GE   = (EE + 255) / 256;
    const int GAG  = (NN / 2 * 32 + 255) / 256;   // 2 nodes per warp -> 3125
    const int GGX  = (NN + 63) / 64;
    const int GGH  = (NN + 127) / 128;

    // ---- setup + CSR ----
    launch_pdl(k_init, 278, 256, 0, false, (const int*)ei, W1, W2, Wout, b1, b2);
    launch_pdl(k_count, GE, 256, 0, true, ei);
    launch_pdl(k_rowoff, NB, 256, 0, true);
    launch_pdl(k_fill, GE, 256, 0, true, ei);

    // ---- Block 1: h1 = relu(A^2(x@W1^2) + sdeg*(b1@W1) + deg*b1) ----
    launch_pdl(k_gemm_x, GGX, 256, SMX, true, x, Wp1, (unsigned*)f16a);
    launch_pdl(k_agg_hh<true>, GAG, 256, 0, true,
               (const uint4*)f16a, (uint4*)f16b);
    launch_pdl(k_agg_epi, GAG, 256, 0, true,
               (const uint4*)f16b, (const float*)bW1, b1, (uint4*)f16c);

    // ---- Block 2: h2 = relu(A^2(h1@W2^2) + sdeg*(b2@W2) + deg*b2) ----
    launch_pdl(k_gemm_h, GGH, 256, SMH, true, f16c, Wp2, (unsigned*)f16a);
    launch_pdl(k_agg_hh<false>, GAG, 256, 0, true,
               (const uint4*)f16a, (uint4*)f16b);
    launch_pdl(k_agg_epi, GAG, 256, 0, true,
               (const uint4*)f16b, (const float*)bW2, b2, (uint4*)f16c);

    // ---- Output: out = h2 @ Wout + bout ----
    launch_pdl(k_gemm_out, GGH, 256, SMO, true, f16c, WpO, bout, out);
}

// round 16
// speedup vs baseline: 1.3708x; 1.3708x over previous
#include <cuda_runtime.h>
#include <cuda_fp16.h>
#include <cstdint>
#include <cstddef>
#include <cstring>

#define NN   50000
#define EE   600000
#define DD   128
#define OUTD 64
#define NB   ((NN + 255) / 256)   // 196 scan blocks

// ---------------------------------------------------------------------------
// Scratch state (no allocations allowed -> __device__ globals)
// ---------------------------------------------------------------------------
__device__ int      g_counts[NN];
__device__ int      g_rowoff[NN + 1];
__device__ unsigned g_packed[EE];          // (ordinal<<17) | dst ; ~0u invalid
__device__ int      g_csrsrc[EE];
__device__ float    g_deg[NN];
__device__ float    g_sdeg[NN];
__device__ uint2    g_f16a[(size_t)NN * DD / 4];   // z1 / z2
__device__ uint2    g_f16b[(size_t)NN * DD / 4];   // t  / u
__device__ uint2    g_f16c[(size_t)NN * DD / 4];   // h1 / h2
__device__ float    g_bW1[DD];
__device__ float    g_bW2[DD];
// Weight tiles in k-pair split-fp16 layout: element (p, n) packs
//   .x = half2( hi(W[2p][n]), hi(W[2p+1][n]) ), .y = half2( lo residuals )
__device__ float2   g_Wp1[(DD / 2) * DD];    // split(W1@W1)
__device__ float2   g_Wp2[(DD / 2) * DD];    // split(W2@W2)
__device__ float2   g_WpO[(DD / 2) * OUTD];  // split(Wout)
__device__ int      g_is32;                  // sticky: 1 iff int32 detected

// ---------------------------------------------------------------------------
// helpers
// ---------------------------------------------------------------------------
__device__ __forceinline__ unsigned h2_bits(__half2 h) {
    unsigned u; memcpy(&u, &h, 4); return u;
}

__device__ __forceinline__ float2 pack_pair(float w0, float w1) {
    __half h0 = __float2half_rn(w0), h1 = __float2half_rn(w1);
    float r0 = w0 - __half2float(h0);
    float r1 = w1 - __half2float(h1);
    __half2 hi = __halves2half2(h0, h1);
    __half2 lo = __floats2half2_rn(r0, r1);
    float2 o;
    o.x = __uint_as_float(h2_bits(hi));
    o.y = __uint_as_float(h2_bits(lo));
    return o;
}

__device__ __forceinline__ void mma_f16(float c[4], unsigned a0, unsigned a1,
                                        unsigned a2, unsigned a3,
                                        unsigned b0, unsigned b1) {
    asm volatile(
        "mma.sync.aligned.m16n8k16.row.col.f32.f16.f16.f32 "
        "{%0,%1,%2,%3}, {%4,%5,%6,%7}, {%8,%9}, {%0,%1,%2,%3};"
        : "+f"(c[0]), "+f"(c[1]), "+f"(c[2]), "+f"(c[3])
        : "r"(a0), "r"(a1), "r"(a2), "r"(a3), "r"(b0), "r"(b1));
}

__device__ __forceinline__ void split2(float2 a, unsigned& hi, unsigned& lo) {
    __half2 h = __floats2half2_rn(a.x, a.y);
    float r0 = a.x - __low2float(h);
    float r1 = a.y - __high2float(h);
    __half2 l = __floats2half2_rn(r0, r1);
    hi = h2_bits(h);
    lo = h2_bits(l);
}

__device__ __forceinline__ void acc_add(float4& a, uint2 u) {
    __half2 p0, p1;
    memcpy(&p0, &u.x, 4); memcpy(&p1, &u.y, 4);
    float2 f0 = __half22float2(p0);
    float2 f1 = __half22float2(p1);
    a.x += f0.x; a.y += f0.y; a.z += f1.x; a.w += f1.y;
}

__device__ __forceinline__ int load_edge(const void* ei, int idx, int is32) {
    if (is32) return ((const int*)ei)[idx];
    return (int)((const long long*)ei)[idx];
}

// 3x-split fp16 mainloop, fp32 A-smem tile (stride 132), split-W tile.
template <int NT, int WS>
__device__ __forceinline__ void tc_loop(const float* Asm, const float2* Wsm,
                                        int r0, int cb, int gid, int tig,
                                        float (*c)[4]) {
    #pragma unroll
    for (int ks = 0; ks < 8; ++ks) {
        int k0 = ks * 16;
        float2 aP0 = *(const float2*)(Asm + (r0 + gid) * 132 + k0 + 2 * tig);
        float2 aP1 = *(const float2*)(Asm + (r0 + gid + 8) * 132 + k0 + 2 * tig);
        float2 aP2 = *(const float2*)(Asm + (r0 + gid) * 132 + k0 + 2 * tig + 8);
        float2 aP3 = *(const float2*)(Asm + (r0 + gid + 8) * 132 + k0 + 2 * tig + 8);
        unsigned ah0, al0, ah1, al1, ah2, al2, ah3, al3;
        split2(aP0, ah0, al0);
        split2(aP1, ah1, al1);
        split2(aP2, ah2, al2);
        split2(aP3, ah3, al3);
        const float2* Wr0 = Wsm + (ks * 8 + tig) * WS + cb;
        const float2* Wr1 = Wsm + (ks * 8 + tig + 4) * WS + cb;
        #pragma unroll
        for (int nt = 0; nt < NT; ++nt) {
            float2 w0 = Wr0[nt * 8 + gid];
            float2 w1 = Wr1[nt * 8 + gid];
            unsigned bh0 = __float_as_uint(w0.x), bl0 = __float_as_uint(w0.y);
            unsigned bh1 = __float_as_uint(w1.x), bl1 = __float_as_uint(w1.y);
            mma_f16(c[nt], ah0, ah1, ah2, ah3, bh0, bh1);   // Ah*Wh
            mma_f16(c[nt], al0, al1, al2, al3, bh0, bh1);   // Al*Wh
            mma_f16(c[nt], ah0, ah1, ah2, ah3, bl0, bl1);   // Ah*Wl
        }
    }
}

// 2-term mainloop for EXACT fp16 A (lo(A) == 0): D = A*Wh + A*Wl.
// A smem: unsigned half2-pairs, stride 68 (conflict-free fragment loads).
template <int NT, int WS>
__device__ __forceinline__ void tc_loop16(const unsigned* Asm16,
                                          const float2* Wsm,
                                          int r0, int gid, int tig,
                                          float (*c)[4]) {
    #pragma unroll
    for (int ks = 0; ks < 8; ++ks) {
        int kp = ks * 8;
        unsigned a0 = Asm16[(r0 + gid) * 68 + kp + tig];
        unsigned a1 = Asm16[(r0 + gid + 8) * 68 + kp + tig];
        unsigned a2 = Asm16[(r0 + gid) * 68 + kp + tig + 4];
        unsigned a3 = Asm16[(r0 + gid + 8) * 68 + kp + tig + 4];
        const float2* Wr0 = Wsm + (kp + tig) * WS;
        const float2* Wr1 = Wsm + (kp + tig + 4) * WS;
        #pragma unroll
        for (int nt = 0; nt < NT; ++nt) {
            float2 w0 = Wr0[nt * 8 + gid];
            float2 w1 = Wr1[nt * 8 + gid];
            unsigned bh0 = __float_as_uint(w0.x), bl0 = __float_as_uint(w0.y);
            unsigned bh1 = __float_as_uint(w1.x), bl1 = __float_as_uint(w1.y);
            mma_f16(c[nt], a0, a1, a2, a3, bh0, bh1);   // A*Wh
            mma_f16(c[nt], a0, a1, a2, a3, bl0, bl1);   // A*Wl
        }
    }
}

// ---------------------------------------------------------------------------
// Init (one launch): [0,196): zero counts + int-width detect; [196,278): prep
// ---------------------------------------------------------------------------
__global__ void k_init(const int* __restrict__ eiw,
                       const float* __restrict__ W1, const float* __restrict__ W2,
                       const float* __restrict__ Wout,
                       const float* __restrict__ b1, const float* __restrict__ b2) {
    int blk = blockIdx.x;
    int tid = threadIdx.x;
    if (blk < 196) {
        int i = blk * 256 + tid;
        if (i < NN) g_counts[i] = 0;
        // sticky detection: int64 little-endian has zero hi words; idempotent
        if (i < 4096 && eiw[2 * i + 1] != 0) g_is32 = 1;
    } else {
        int b = blk - 196;
        if (b < 64) {
            const float* W = (b < 32) ? W1 : W2;
            float2* O = (b < 32) ? g_Wp1 : g_Wp2;
            int idx = (b & 31) * 256 + tid;
            int pp = idx >> 7, n = idx & 127;
            int r0 = 2 * pp, r1 = 2 * pp + 1;
            float s0 = 0.f, s1 = 0.f;
            #pragma unroll 8
            for (int k = 0; k < DD; ++k) {
                float wc = W[k * DD + n];
                s0 += W[r0 * DD + k] * wc;
                s1 += W[r1 * DD + k] * wc;
            }
            O[idx] = pack_pair(s0, s1);
        } else if (b < 80) {
            int idx = (b - 64) * 256 + tid;
            int pp = idx >> 6, n = idx & 63;
            float w0 = Wout[(2 * pp) * OUTD + n];
            float w1 = Wout[(2 * pp + 1) * OUTD + n];
            g_WpO[idx] = pack_pair(w0, w1);
        } else {
            const float* bb = (b == 80) ? b1 : b2;
            const float* W  = (b == 80) ? W1 : W2;
            float* bw = (b == 80) ? g_bW1 : g_bW2;
            if (tid < DD) {
                float s = 0.f;
                #pragma unroll 8
                for (int k = 0; k < DD; ++k) s += bb[k] * W[k * DD + tid];
                bw[tid] = s;
            }
        }
    }
}

// Count in-degree; pack (ordinal<<17)|dst so k_fill never re-reads dst.
__global__ void k_count(const void* __restrict__ ei) {
    int e = blockIdx.x * blockDim.x + threadIdx.x;
    if (e >= EE) return;
    int is32 = g_is32;
    int dst = load_edge(ei, EE + e, is32);
    unsigned pk = 0xFFFFFFFFu;
    if ((unsigned)dst < (unsigned)NN) {
        int ord = atomicAdd(&g_counts[dst], 1);
        pk = ((unsigned)ord << 17) | (unsigned)dst;
    }
    g_packed[e] = pk;
}

// Self-summing scan: each block reduces counts[0 .. blockIdx*256) for its
// prefix (L2-resident), then local scan.
__global__ void k_rowoff() {
    __shared__ int ws[8];
    __shared__ int s_prefix;
    int tid = threadIdx.x;
    int lane = tid & 31, wid = tid >> 5;

    int lim = blockIdx.x * 256;
    int pi = 0;
    for (int j = tid; j < lim; j += 256) pi += g_counts[j];
    #pragma unroll
    for (int o = 16; o > 0; o >>= 1) pi += __shfl_down_sync(0xffffffffu, pi, o);
    if (lane == 0) ws[wid] = pi;
    __syncthreads();
    if (tid == 0) {
        int s = 0;
        #pragma unroll
        for (int w = 0; w < 8; ++w) s += ws[w];
        s_prefix = s;
    }
    __syncthreads();
    int prefix = s_prefix;
    __syncthreads();

    int i = blockIdx.x * 256 + tid;
    int v = (i < NN) ? g_counts[i] : 0;
    int x = v;
    #pragma unroll
    for (int o = 1; o < 32; o <<= 1) {
        int t = __shfl_up_sync(0xffffffffu, x, o);
        if (lane >= o) x += t;
    }
    if (lane == 31) ws[wid] = x;
    __syncthreads();
    if (wid == 0) {
        int y = (lane < 8) ? ws[lane] : 0;
        #pragma unroll
        for (int o = 1; o < 8; o <<= 1) {
            int t = __shfl_up_sync(0xffffffffu, y, o);
            if (lane >= o) y += t;
        }
        if (lane < 8) ws[lane] = y;
    }
    __syncthreads();
    int excl = x - v + (wid ? ws[wid - 1] : 0) + prefix;
    if (i < NN) {
        g_rowoff[i] = excl;
        g_deg[i] = (float)v;
        if (i == NN - 1) g_rowoff[NN] = excl + v;
    }
}

// Fill CSR — atomic-free; reads only src half + packed(dst,ordinal).
__global__ void k_fill(const void* __restrict__ ei) {
    int e = blockIdx.x * blockDim.x + threadIdx.x;
    if (e >= EE) return;
    unsigned pk = g_packed[e];
    if (pk == 0xFFFFFFFFu) return;
    int dst = (int)(pk & 0x1FFFFu);
    int ord = (int)(pk >> 17);
    int is32 = g_is32;
    int src = load_edge(ei, e, is32);
    if ((unsigned)src >= (unsigned)NN) src = 0;
    g_csrsrc[g_rowoff[dst] + ord] = src;
}

// ---------------------------------------------------------------------------
// Aggregation over fp16 rows. One warp/node; lane owns 4 cols (uint2).
// ---------------------------------------------------------------------------
template <bool SDEG>
__device__ __forceinline__ float4 gather_row(const uint2* __restrict__ in,
                                             int node, int lane, float& sd) {
    float4 acc = make_float4(0.f, 0.f, 0.f, 0.f);
    int beg = g_rowoff[node], end = g_rowoff[node + 1];
    int e = beg;
    for (; e + 4 <= end; e += 4) {
        int s0 = g_csrsrc[e];
        int s1 = g_csrsrc[e + 1];
        int s2 = g_csrsrc[e + 2];
        int s3 = g_csrsrc[e + 3];
        uint2 u0 = in[(size_t)s0 * 32 + lane];
        uint2 u1 = in[(size_t)s1 * 32 + lane];
        uint2 u2 = in[(size_t)s2 * 32 + lane];
        uint2 u3 = in[(size_t)s3 * 32 + lane];
        if (SDEG) sd += (g_deg[s0] + g_deg[s1]) + (g_deg[s2] + g_deg[s3]);
        acc_add(acc, u0); acc_add(acc, u1);
        acc_add(acc, u2); acc_add(acc, u3);
    }
    for (; e < end; ++e) {
        int s0 = g_csrsrc[e];
        uint2 u0 = in[(size_t)s0 * 32 + lane];
        if (SDEG) sd += g_deg[s0];
        acc_add(acc, u0);
    }
    return acc;
}

// Plain gather -> fp16 (optionally computing sdeg on pass 1)
template <bool SDEG>
__global__ void __launch_bounds__(256) k_agg_hh(const uint2* __restrict__ in,
                                                uint2* __restrict__ out) {
    int w = (blockIdx.x * blockDim.x + threadIdx.x) >> 5;
    int lane = threadIdx.x & 31;
    if (w >= NN) return;
    float sd = 0.f;
    float4 acc = gather_row<SDEG>(in, w, lane, sd);
    __half2 h0 = __floats2half2_rn(acc.x, acc.y);
    __half2 h1 = __floats2half2_rn(acc.z, acc.w);
    uint2 o; o.x = h2_bits(h0); o.y = h2_bits(h1);
    out[(size_t)w * 32 + lane] = o;
    if (SDEG && lane == 0) g_sdeg[w] = sd;
}

// Gather + pool epilogue: h = relu(acc + sdeg*bw + deg*bv) -> fp16
__global__ void __launch_bounds__(256) k_agg_epi(const uint2* __restrict__ in,
                                                 const float* __restrict__ bw,
                                                 const float* __restrict__ bv,
                                                 uint2* __restrict__ out) {
    int w = (blockIdx.x * blockDim.x + threadIdx.x) >> 5;
    int lane = threadIdx.x & 31;
    if (w >= NN) return;
    float sd = 0.f;
    float4 acc = gather_row<false>(in, w, lane, sd);
    float s = g_sdeg[w], d = g_deg[w];
    float4 bw4 = ((const float4*)bw)[lane];
    float4 bv4 = ((const float4*)bv)[lane];
    acc.x = fmaxf(acc.x + s * bw4.x + d * bv4.x, 0.f);
    acc.y = fmaxf(acc.y + s * bw4.y + d * bv4.y, 0.f);
    acc.z = fmaxf(acc.z + s * bw4.z + d * bv4.z, 0.f);
    acc.w = fmaxf(acc.w + s * bw4.w + d * bv4.w, 0.f);
    __half2 h0 = __floats2half2_rn(acc.x, acc.y);
    __half2 h1 = __floats2half2_rn(acc.z, acc.w);
    uint2 o; o.x = h2_bits(h0); o.y = h2_bits(h1);
    out[(size_t)w * 32 + lane] = o;
}

// ---------------------------------------------------------------------------
// GEMM 1: z1 = x @ Wp1  (fp32 A, 3-term, no bias), fp16 out. 64x128 tile.
// ---------------------------------------------------------------------------
__global__ void __launch_bounds__(256, 2)
k_gemm_x(const float* __restrict__ A, const float2* __restrict__ Wp,
         unsigned* __restrict__ C16) {
    extern __shared__ char smraw[];
    float*  Asm = (float*)smraw;                               // [64][132]
    float2* Wsm = (float2*)(smraw + 64 * 132 * sizeof(float)); // [64][132]

    const int tid = threadIdx.x;
    const int row0 = blockIdx.x * 64;

    #pragma unroll 4
    for (int idx = tid; idx < 64 * 128; idx += 256) {
        int p = idx >> 7, n = idx & 127;
        Wsm[p * 132 + n] = Wp[idx];
    }
    {
        const float4* Ag = (const float4*)A;
        #pragma unroll
        for (int it = 0; it < 8; ++it) {
            int idx = it * 256 + tid;
            int r = idx >> 5, kq = idx & 31;
            float4 v = make_float4(0.f, 0.f, 0.f, 0.f);
            if (row0 + r < NN) v = Ag[(size_t)(row0 + r) * 32 + kq];
            *(float4*)(Asm + r * 132 + kq * 4) = v;
        }
    }
    __syncthreads();

    const int warp = tid >> 5, lane = tid & 31;
    const int gid = lane >> 2, tig = lane & 3;
    const int r0 = (warp & 3) * 16;
    const int cb = (warp >> 2) * 64;

    float c[8][4];
    #pragma unroll
    for (int nt = 0; nt < 8; ++nt)
        #pragma unroll
        for (int q = 0; q < 4; ++q) c[nt][q] = 0.f;

    tc_loop<8, 132>(Asm, Wsm, r0, cb, gid, tig, c);

    int rA = row0 + r0 + gid;
    int rB = rA + 8;
    #pragma unroll
    for (int nt = 0; nt < 8; ++nt) {
        int col = cb + nt * 8 + 2 * tig;
        if (rA < NN)
            C16[(size_t)rA * 64 + (col >> 1)] =
                h2_bits(__floats2half2_rn(c[nt][0], c[nt][1]));
        if (rB < NN)
            C16[(size_t)rB * 64 + (col >> 1)] =
                h2_bits(__floats2half2_rn(c[nt][2], c[nt][3]));
    }
}

// ---------------------------------------------------------------------------
// GEMM 2: z2 = h1 @ Wp2  (EXACT fp16 A, 2-term), fp16 out. 128x128 tile.
// ---------------------------------------------------------------------------
__global__ void __launch_bounds__(256, 2)
k_gemm_h(const uint2* __restrict__ A16, const float2* __restrict__ Wp,
         unsigned* __restrict__ C16) {
    extern __shared__ char smraw[];
    unsigned* Asm16 = (unsigned*)smraw;                             // [128][68]
    float2*   Wsm = (float2*)(smraw + 128 * 68 * sizeof(unsigned)); // [64][132]

    const int tid = threadIdx.x;
    const int row0 = blockIdx.x * 128;

    #pragma unroll 8
    for (int idx = tid; idx < 64 * 128; idx += 256) {
        int p = idx >> 7, n = idx & 127;
        Wsm[p * 132 + n] = Wp[idx];
    }
    {
        const uint4* Ag = (const uint4*)A16;
        #pragma unroll
        for (int it = 0; it < 8; ++it) {
            int idx = it * 256 + tid;
            int r = idx >> 4, q = idx & 15;
            uint4 v = make_uint4(0u, 0u, 0u, 0u);
            if (row0 + r < NN) v = Ag[(size_t)(row0 + r) * 16 + q];
            *(uint4*)(Asm16 + r * 68 + q * 4) = v;
        }
    }
    __syncthreads();

    const int warp = tid >> 5, lane = tid & 31;
    const int gid = lane >> 2, tig = lane & 3;
    const int r0 = warp * 16;

    float c[16][4];
    #pragma unroll
    for (int nt = 0; nt < 16; ++nt)
        #pragma unroll
        for (int q = 0; q < 4; ++q) c[nt][q] = 0.f;

    tc_loop16<16, 132>(Asm16, Wsm, r0, gid, tig, c);

    int rA = row0 + r0 + gid;
    int rB = rA + 8;
    #pragma unroll
    for (int nt = 0; nt < 16; ++nt) {
        int col = nt * 8 + 2 * tig;
        if (rA < NN)
            C16[(size_t)rA * 64 + (col >> 1)] =
                h2_bits(__floats2half2_rn(c[nt][0], c[nt][1]));
        if (rB < NN)
            C16[(size_t)rB * 64 + (col >> 1)] =
                h2_bits(__floats2half2_rn(c[nt][2], c[nt][3]));
    }
}

// ---------------------------------------------------------------------------
// GEMM out: out = h2 @ WpO + bout  (EXACT fp16 A, 2-term), fp32 out.
// ---------------------------------------------------------------------------
__global__ void __launch_bounds__(256, 2)
k_gemm_out(const uint2* __restrict__ A16, const float2* __restrict__ WpO,
           const float* __restrict__ bvo, float* __restrict__ out) {
    extern __shared__ char smraw[];
    unsigned* Asm16 = (unsigned*)smraw;                             // [128][68]
    float2*   Wsm = (float2*)(smraw + 128 * 68 * sizeof(unsigned)); // [64][68]

    const int tid = threadIdx.x;
    const int row0 = blockIdx.x * 128;

    #pragma unroll 4
    for (int idx = tid; idx < 64 * 64; idx += 256) {
        int p = idx >> 6, n = idx & 63;
        Wsm[p * 68 + n] = WpO[idx];
    }
    {
        const uint4* Ag = (const uint4*)A16;
        #pragma unroll
        for (int it = 0; it < 8; ++it) {
            int idx = it * 256 + tid;
            int r = idx >> 4, q = idx & 15;
            uint4 v = make_uint4(0u, 0u, 0u, 0u);
            if (row0 + r < NN) v = Ag[(size_t)(row0 + r) * 16 + q];
            *(uint4*)(Asm16 + r * 68 + q * 4) = v;
        }
    }
    __syncthreads();

    const int warp = tid >> 5, lane = tid & 31;
    const int gid = lane >> 2, tig = lane & 3;
    const int r0 = warp * 16;

    float c[8][4];
    #pragma unroll
    for (int nt = 0; nt < 8; ++nt)
        #pragma unroll
        for (int q = 0; q < 4; ++q) c[nt][q] = 0.f;

    tc_loop16<8, 68>(Asm16, Wsm, r0, gid, tig, c);

    int rA = row0 + r0 + gid;
    int rB = rA + 8;
    #pragma unroll
    for (int nt = 0; nt < 8; ++nt) {
        int col = nt * 8 + 2 * tig;
        float v0 = bvo[col], v1 = bvo[col + 1];
        if (rA < NN)
            *(float2*)&out[(size_t)rA * OUTD + col] =
                make_float2(c[nt][0] + v0, c[nt][1] + v1);
        if (rB < NN)
            *(float2*)&out[(size_t)rB * OUTD + col] =
                make_float2(c[nt][2] + v0, c[nt][3] + v1);
    }
}

// ---------------------------------------------------------------------------
// Launch: 11 kernels, plain stream-ordered launches (PDL reverted)
// ---------------------------------------------------------------------------
extern "C" void kernel_launch(void* const* d_in, const int* in_sizes, int n_in,
                              void* d_out, int out_size) {
    const float* x    = (const float*)d_in[0];
    const void*  ei   = d_in[1];
    const float* W1   = (const float*)d_in[2];
    const float* b1   = (const float*)d_in[3];
    const float* W2   = (const float*)d_in[4];
    const float* b2   = (const float*)d_in[5];
    const float* Wout = (const float*)d_in[6];
    const float* bout = (const float*)d_in[7];
    float* out = (float*)d_out;

    void *pbW1, *pbW2, *pWp1, *pWp2, *pWpO, *pa, *pb, *pc;
    cudaGetSymbolAddress(&pbW1, g_bW1);
    cudaGetSymbolAddress(&pbW2, g_bW2);
    cudaGetSymbolAddress(&pWp1, g_Wp1);
    cudaGetSymbolAddress(&pWp2, g_Wp2);
    cudaGetSymbolAddress(&pWpO, g_WpO);
    cudaGetSymbolAddress(&pa, g_f16a);
    cudaGetSymbolAddress(&pb, g_f16b);
    cudaGetSymbolAddress(&pc, g_f16c);
    float*  bW1 = (float*)pbW1;
    float*  bW2 = (float*)pbW2;
    float2* Wp1 = (float2*)pWp1;
    float2* Wp2 = (float2*)pWp2;
    float2* WpO = (float2*)pWpO;
    uint2*  f16a = (uint2*)pa;
    uint2*  f16b = (uint2*)pb;
    uint2*  f16c = (uint2*)pc;

    const size_t SMX = 64 * 132 * sizeof(float) + 64 * 132 * sizeof(float2);    // ~99 KB
    const size_t SMH = 128 * 68 * sizeof(unsigned) + 64 * 132 * sizeof(float2); // 100 KB
    const size_t SMO = 128 * 68 * sizeof(unsigned) + 64 * 68 * sizeof(float2);  // ~68 KB
    cudaFuncSetAttribute(k_gemm_x,
                         cudaFuncAttributeMaxDynamicSharedMemorySize, (int)SMX);
    cudaFuncSetAttribute(k_gemm_h,
                         cudaFuncAttributeMaxDynamicSharedMemorySize, (int)SMH);
    cudaFuncSetAttribute(k_gemm_out,
                         cudaFuncAttributeMaxDynamicSharedMemorySize, (int)SMO);

    const int GE   = (EE + 255) / 256;
    const int GAG  = (NN * 32 + 255) / 256;   // one warp per node
    const int GGX  = (NN + 63) / 64;
    const int GGH  = (NN + 127) / 128;

    // ---- setup + CSR ----
    k_init<<<278, 256>>>((const int*)ei, W1, W2, Wout, b1, b2);
    k_count<<<GE, 256>>>(ei);
    k_rowoff<<<NB, 256>>>();
    k_fill<<<GE, 256>>>(ei);

    // ---- Block 1: h1 = relu(A^2(x@W1^2) + sdeg*(b1@W1) + deg*b1) ----
    k_gemm_x<<<GGX, 256, SMX>>>(x, Wp1, (unsigned*)f16a);     // z1
    k_agg_hh<true><<<GAG, 256>>>(f16a, f16b);                 // t = A(z1), sdeg
    k_agg_epi<<<GAG, 256>>>(f16b, bW1, b1, f16c);             // h1

    // ---- Block 2: h2 = relu(A^2(h1@W2^2) + sdeg*(b2@W2) + deg*b2) ----
    k_gemm_h<<<GGH, 256, SMH>>>(f16c, Wp2, (unsigned*)f16a);  // z2 (exact fp16)
    k_agg_hh<false><<<GAG, 256>>>(f16a, f16b);                // u = A(z2)
    k_agg_epi<<<GAG, 256>>>(f16b, bW2, b2, f16c);             // h2

    // ---- Output: out = h2 @ Wout + bout ----
    k_gemm_out<<<GGH, 256, SMO>>>(f16c, WpO, bout, out);
}